// round 14
// baseline (speedup 1.0000x reference)
#include <cuda_runtime.h>
#include <cuda_fp16.h>
#include <cstdint>
#include <math.h>

// ============================================================================
// QAConv fp16 persistent, 512-thread CTAs: s[g,p,i,j] = <ker[p,i,:],
// gal[g,:,j]> (channel-L2-normalized), score = sigmoid(lbn(fc(bn(...)))/10).
//
// vs R13 (256 thr, warp tile 48x96, 381.7us): 16 warps (4/SMSP) with 4x4 warp
// grid, warp tile 48x48 — deeper latency cover for the legacy-path tensor
// pipe (measured ~75% of the 1024 MACs/cyc/SM ceiling at 2 warps/SMSP).
// Everything else held: persistent CTAs, 3-stage cp.async ring crossing pair
// boundaries, fused dual-max epilogue, fp16 operands + fp16 accumulate.
// ============================================================================

#define G_ 64
#define P_ 64
#define D_ 512
#define HW_ 192
#define NPAIR (G_ * P_)
#define THREADS 512

__device__ __half g_kerA[(size_t)P_ * HW_ * D_];   // [p][i][k] K-major
__device__ __half g_galB[(size_t)G_ * HW_ * D_];   // [g][j][k] K-major
__device__ float g_scale[128 * HW_];               // [z][j] 1/norm

// ------------------------- Kernel 1: column norms --------------------------
__global__ void __launch_bounds__(768) norm_kernel(const float* __restrict__ gal,
                                                   const float* __restrict__ prob) {
    __shared__ float ssum[4][HW_];
    int b = blockIdx.x;                 // 0..127
    int j = threadIdx.x;                // 0..191
    int ty = threadIdx.y;               // 0..3
    const float* src = (b < 64) ? (gal + (size_t)b * D_ * HW_)
                                : (prob + (size_t)(b - 64) * D_ * HW_);
    float ss = 0.f;
#pragma unroll 8
    for (int dd = 0; dd < 128; dd++) {
        float v = src[(size_t)(ty * 128 + dd) * HW_ + j];
        ss += v * v;
    }
    ssum[ty][j] = ss;
    __syncthreads();
    if (ty == 0) {
        ss = ssum[0][j] + ssum[1][j] + ssum[2][j] + ssum[3][j];
        g_scale[b * HW_ + j] = 1.f / fmaxf(sqrtf(ss), 1e-12f);
    }
}

// ------------------ Kernel 2: transpose + scale + f16 ----------------------
__global__ void prep_kernel(const float* __restrict__ gal,
                            const float* __restrict__ prob) {
    __shared__ float tile[32][33];
    __shared__ float fj[32];
    int z = blockIdx.z;                 // 0..127
    int d0 = blockIdx.x * 32;           // 16 tiles
    int j0 = blockIdx.y * 32;           // 6 tiles
    int tx = threadIdx.x, ty = threadIdx.y;  // 32 x 8
    const float* src;
    __half* dst;
    if (z < 64) {
        src = gal + (size_t)z * D_ * HW_;
        dst = g_galB + (size_t)z * HW_ * D_;
    } else {
        src = prob + (size_t)(z - 64) * D_ * HW_;
        dst = g_kerA + (size_t)(z - 64) * HW_ * D_;
    }
#pragma unroll
    for (int r = 0; r < 32; r += 8)
        tile[ty + r][tx] = src[(size_t)(d0 + ty + r) * HW_ + j0 + tx];
    if (ty == 0) fj[tx] = g_scale[z * HW_ + j0 + tx];
    __syncthreads();

    int tid = ty * 32 + tx;
    int jl = tid >> 3;                  // 0..31 (j within tile)
    int d4 = (tid & 7) * 4;             // 0,4,..,28 (d within tile)
    float f = fj[jl];
    __half2 lo = __floats2half2_rn(tile[d4 + 0][jl] * f, tile[d4 + 1][jl] * f);
    __half2 hi = __floats2half2_rn(tile[d4 + 2][jl] * f, tile[d4 + 3][jl] * f);
    uint2 packed = make_uint2(*(uint32_t*)&lo, *(uint32_t*)&hi);
    *(uint2*)(dst + (size_t)(j0 + jl) * D_ + d0 + d4) = packed;
}

// ------------------------------ helpers ------------------------------
__device__ __forceinline__ uint32_t smem_u32(const void* p) {
    return (uint32_t)__cvta_generic_to_shared(p);
}
__device__ __forceinline__ void cpasync16(uint32_t dst, const void* src) {
    asm volatile("cp.async.cg.shared.global [%0], [%1], 16;"
                 :: "r"(dst), "l"(src) : "memory");
}
__device__ __forceinline__ void ldsm4(uint32_t& r0, uint32_t& r1,
                                      uint32_t& r2, uint32_t& r3,
                                      uint32_t addr) {
    asm volatile("ldmatrix.sync.aligned.m8n8.x4.shared.b16 {%0,%1,%2,%3}, [%4];"
                 : "=r"(r0), "=r"(r1), "=r"(r2), "=r"(r3) : "r"(addr));
}
// f16 x f16 -> f16 accumulate. D/C = 2x b32 (4 halves):
//   reg0 = {(row r, col c), (row r, col c+1)}
//   reg1 = {(row r+8, col c), (row r+8, col c+1)}
__device__ __forceinline__ void mma16816h(uint32_t* c, const uint32_t* a,
                                          uint32_t b0, uint32_t b1) {
    asm volatile(
        "mma.sync.aligned.m16n8k16.row.col.f16.f16.f16.f16 "
        "{%0,%1}, {%2,%3,%4,%5}, {%6,%7}, {%0,%1};"
        : "+r"(c[0]), "+r"(c[1])
        : "r"(a[0]), "r"(a[1]), "r"(a[2]), "r"(a[3]), "r"(b0), "r"(b1));
}

#define SWZ(x) ((x) ^ (((x) >> 3) & 0x70))

// SMEM: 3-stage ring; stage = A 192x128B (24KB) + B 192x128B (24KB) = 48KB
#define OFF_BUF    1024
#define CH_BYTES   49152
#define STG(s)     (OFF_BUF + (s) * CH_BYTES)
#define OFF_ROWP   (OFF_BUF + 3 * CH_BYTES)            // rowp[4][192] f32
#define OFF_COLP   (OFF_ROWP + 4 * 192 * 4)            // colp[4][192] f32
#define OFF_RED    (OFF_COLP + 4 * 192 * 4)            // red[16]
#define SMEM_BYTES (OFF_RED + 64)

// Issue all cp.async for chunk c (K in [c*64,(c+1)*64)) of `pair` into stage st
__device__ __forceinline__ void load_chunk(uint32_t sbase, int pair, int c,
                                           int st, int tid) {
    const __half* Ag = g_kerA + (size_t)(pair & 63) * HW_ * D_;
    const __half* Bg = g_galB + (size_t)(pair >> 6) * HW_ * D_;
    const uint32_t sb_ = sbase + STG(st);
#pragma unroll
    for (int i = 0; i < 6; i++) {
        int gid2 = tid + i * THREADS;
        bool isA = gid2 < 1536;
        int lg = isA ? gid2 : gid2 - 1536;
        int row = lg >> 3, seg = lg & 7;
        const __half* src =
            (isA ? Ag : Bg) + (size_t)row * D_ + c * 64 + seg * 8;
        uint32_t dst = sb_ + (isA ? 0 : 24576) + SWZ(row * 128 + seg * 16);
        cpasync16(dst, src);
    }
    asm volatile("cp.async.commit_group;" ::: "memory");
}

// ----------------- Kernel 3: persistent GEMM + fused epilogue -------------
__global__ void __launch_bounds__(THREADS, 1) qaconv_gemm(
    const float* __restrict__ bnw, const float* __restrict__ bnb,
    const float* __restrict__ bnm, const float* __restrict__ bnv,
    const float* __restrict__ fcw, const float* __restrict__ fcb,
    const float* __restrict__ lbnw, const float* __restrict__ lbnb,
    const float* __restrict__ lbnm, const float* __restrict__ lbnv,
    float* __restrict__ out)
{
    extern __shared__ char smem[];
    const uint32_t sbase = smem_u32(smem);
    const int tid = threadIdx.x;
    const int wid = tid >> 5;
    const int lane = tid & 31;
    const int warp_m = wid & 3;        // 4 strips of 48 rows (probe i)
    const int warp_n = wid >> 2;       // 4 strips of 48 cols (gallery j)
    const int bid = blockIdx.x;
    const int gstride = gridDim.x;

    const int T = (NPAIR - bid + gstride - 1) / gstride;   // pairs for this CTA
    if (T <= 0) return;
    const int lastLc = T * 8 - 1;

    const float a_bn = bnw[0] * rsqrtf(bnv[0] + 1e-5f);
    const float b_bn = bnb[0] - bnm[0] * a_bn;
    const float a_lbn = lbnw[0] * rsqrtf(lbnv[0] + 1e-5f);
    const float b0_lbn = lbnb[0] - lbnm[0] * a_lbn;
    const float fcb0 = fcb[0];

    float* rowp = (float*)(smem + OFF_ROWP);   // [4][192]
    float* colp = (float*)(smem + OFF_COLP);   // [4][192]
    float* red  = (float*)(smem + OFF_RED);

    // prologue: first two chunks of first pair
    load_chunk(sbase, bid, 0, 0, tid);
    load_chunk(sbase, bid, 1, 1, tid);

#pragma unroll 1
    for (int t = 0; t < T; t++) {
        const int pair = bid + t * gstride;

        uint32_t acc[3][6][2];           // f16x2 accumulators (48x48 tile)
#pragma unroll
        for (int mt = 0; mt < 3; mt++)
#pragma unroll
            for (int nt = 0; nt < 6; nt++) {
                acc[mt][nt][0] = 0u;
                acc[mt][nt][1] = 0u;
            }

#pragma unroll 1
        for (int c = 0; c < 8; c++) {
            const int lc = t * 8 + c;
            if (lc == lastLc)
                asm volatile("cp.async.wait_group 0;" ::: "memory");
            else
                asm volatile("cp.async.wait_group 1;" ::: "memory");
            __syncthreads();

            const uint32_t ab = sbase + STG(lc % 3);
            const uint32_t bb = ab + 24576;
            const int arowb = (warp_m * 48 + (lane & 15)) * 128;
            const int brow  = warp_n * 48 + (lane & 7) + ((lane >> 4) << 3);
#pragma unroll
            for (int ks = 0; ks < 4; ks++) {
                const int akb = ks * 32 + ((lane >> 4) << 4);
                const int bkb = ks * 32 + (((lane >> 3) & 1) << 4);
                uint32_t a[3][4];
#pragma unroll
                for (int mt = 0; mt < 3; mt++)
                    ldsm4(a[mt][0], a[mt][1], a[mt][2], a[mt][3],
                          ab + SWZ(arowb + mt * 2048 + akb));
                uint32_t bf[3][4];
#pragma unroll
                for (int nt2 = 0; nt2 < 3; nt2++)
                    ldsm4(bf[nt2][0], bf[nt2][1], bf[nt2][2], bf[nt2][3],
                          bb + SWZ((brow + nt2 * 16) * 128 + bkb));
#pragma unroll
                for (int mt = 0; mt < 3; mt++)
#pragma unroll
                    for (int nt2 = 0; nt2 < 3; nt2++) {
                        mma16816h(acc[mt][nt2 * 2 + 0], a[mt], bf[nt2][0], bf[nt2][1]);
                        mma16816h(acc[mt][nt2 * 2 + 1], a[mt], bf[nt2][2], bf[nt2][3]);
                    }
            }
            // prefetch chunk lc+2 (may belong to the next pair)
            const int lcn = lc + 2;
            if (lcn <= lastLc) {
                const int pairN = bid + (lcn >> 3) * gstride;
                load_chunk(sbase, pairN, lcn & 7, lcn % 3, tid);
            }
        }

        // -------- epilogue: dual max + BN/fc/LBN/sigmoid (overlaps next loads)
        // acc[mt][nt][0] = {(r,c),(r,c+1)}, [1] = {(r+8,c),(r+8,c+1)}
        //   r = warp_m*48 + mt*16 + lane/4, c = warp_n*48 + nt*8 + (lane%4)*2
        const __half2 NEGINF = __float2half2_rn(-60000.f);

        float rm[6];
#pragma unroll
        for (int mt = 0; mt < 3; mt++) {
            __half2 m0 = NEGINF, m1 = NEGINF;
#pragma unroll
            for (int nt = 0; nt < 6; nt++) {
                m0 = __hmax2(m0, *(__half2*)&acc[mt][nt][0]);
                m1 = __hmax2(m1, *(__half2*)&acc[mt][nt][1]);
            }
            rm[2 * mt]     = fmaxf(__low2float(m0), __high2float(m0));
            rm[2 * mt + 1] = fmaxf(__low2float(m1), __high2float(m1));
        }
#pragma unroll
        for (int i = 0; i < 6; i++) {
            rm[i] = fmaxf(rm[i], __shfl_xor_sync(0xffffffffu, rm[i], 1));
            rm[i] = fmaxf(rm[i], __shfl_xor_sync(0xffffffffu, rm[i], 2));
        }
        if ((lane & 3) == 0) {
            int rbase = warp_m * 48 + (lane >> 2);
#pragma unroll
            for (int mt = 0; mt < 3; mt++) {
                rowp[warp_n * 192 + rbase + mt * 16]     = rm[2 * mt];
                rowp[warp_n * 192 + rbase + mt * 16 + 8] = rm[2 * mt + 1];
            }
        }

        float cm[12];
#pragma unroll
        for (int nt = 0; nt < 6; nt++) {
            __half2 mc = NEGINF;
#pragma unroll
            for (int mt = 0; mt < 3; mt++)
                mc = __hmax2(mc, __hmax2(*(__half2*)&acc[mt][nt][0],
                                         *(__half2*)&acc[mt][nt][1]));
            cm[2 * nt]     = __low2float(mc);
            cm[2 * nt + 1] = __high2float(mc);
        }
#pragma unroll
        for (int i = 0; i < 12; i++) {
            cm[i] = fmaxf(cm[i], __shfl_xor_sync(0xffffffffu, cm[i], 4));
            cm[i] = fmaxf(cm[i], __shfl_xor_sync(0xffffffffu, cm[i], 8));
            cm[i] = fmaxf(cm[i], __shfl_xor_sync(0xffffffffu, cm[i], 16));
        }
        if (lane < 4) {
            int cbase = warp_n * 48 + lane * 2;
#pragma unroll
            for (int nt = 0; nt < 6; nt++) {
                colp[warp_m * 192 + cbase + nt * 8]     = cm[2 * nt];
                colp[warp_m * 192 + cbase + nt * 8 + 1] = cm[2 * nt + 1];
            }
        }
        __syncthreads();

        float part = 0.f;
        if (tid < 192) {
            float cmax = fmaxf(fmaxf(colp[tid], colp[192 + tid]),
                               fmaxf(colp[384 + tid], colp[576 + tid]));
            float rmax = fmaxf(fmaxf(rowp[tid], rowp[192 + tid]),
                               fmaxf(rowp[384 + tid], rowp[576 + tid]));
            part = fcw[tid]       * (a_bn * cmax + b_bn)   // s.max(axis=2), idx j
                 + fcw[192 + tid] * (a_bn * rmax + b_bn);  // s.max(axis=3), idx i
        }
#pragma unroll
        for (int o = 16; o > 0; o >>= 1)
            part += __shfl_down_sync(0xffffffffu, part, o);
        if (lane == 0) red[wid] = part;
        __syncthreads();
        if (tid == 0) {
            float s = 0.f;
#pragma unroll
            for (int i = 0; i < 16; i++) s += red[i];
            s += fcb0;
            float y = s * a_lbn + b0_lbn;
            out[pair] = 1.f / (1.f + expf(-y * 0.1f));
        }
    }
}

// ------------------------------ launch ---------------------------------------
extern "C" void kernel_launch(void* const* d_in, const int* in_sizes, int n_in,
                              void* d_out, int out_size) {
    const float* gal  = (const float*)d_in[0];
    const float* prob = (const float*)d_in[1];
    const float* bnw  = (const float*)d_in[2];
    const float* bnb  = (const float*)d_in[3];
    const float* bnm  = (const float*)d_in[4];
    const float* bnv  = (const float*)d_in[5];
    const float* fcw  = (const float*)d_in[6];
    const float* fcb  = (const float*)d_in[7];
    const float* lbnw = (const float*)d_in[8];
    const float* lbnb = (const float*)d_in[9];
    const float* lbnm = (const float*)d_in[10];
    const float* lbnv = (const float*)d_in[11];
    float* out = (float*)d_out;

    int sms = 0;
    cudaDeviceGetAttribute(&sms, cudaDevAttrMultiProcessorCount, 0);
    if (sms <= 0) sms = 148;
    if (sms > NPAIR) sms = NPAIR;

    cudaFuncSetAttribute(qaconv_gemm, cudaFuncAttributeMaxDynamicSharedMemorySize,
                         SMEM_BYTES);

    norm_kernel<<<128, dim3(192, 4)>>>(gal, prob);
    prep_kernel<<<dim3(16, 6, 128), dim3(32, 8)>>>(gal, prob);
    qaconv_gemm<<<sms, THREADS, SMEM_BYTES>>>(bnw, bnb, bnm, bnv, fcw, fcb,
                                              lbnw, lbnb, lbnm, lbnv, out);
}

// round 16
// speedup vs baseline: 1.0412x; 1.0412x over previous
#include <cuda_runtime.h>
#include <cuda_fp16.h>
#include <cstdint>
#include <math.h>

// ============================================================================
// QAConv fp16 persistent (R13 GEMM verbatim + high-occupancy norm kernel):
// s[g,p,i,j] = <ker[p,i,:], gal[g,:,j]> (channel-L2-normalized),
// score = sigmoid(lbn(fc(bn([colmax|rowmax])))/10).
//
// R15's 4-stage/2-subchunk sync reduction raced (prefetch into stages other
// warps were still reading). Reverted to the proven 3-stage ring where the
// prefetch target is the previous chunk's stage (fenced by the iteration-top
// __syncthreads). Kept: 512-CTA norm kernel (was 128 CTAs / 37% occupancy).
// ============================================================================

#define G_ 64
#define P_ 64
#define D_ 512
#define HW_ 192
#define NPAIR (G_ * P_)

__device__ __half g_kerA[(size_t)P_ * HW_ * D_];   // [p][i][k] K-major
__device__ __half g_galB[(size_t)G_ * HW_ * D_];   // [g][j][k] K-major
__device__ float g_scale[128 * HW_];               // [z][j] 1/norm

// ------------------------- Kernel 1: column norms --------------------------
// grid (128, 4), block (48, 16): 512 CTAs for full-chip occupancy.
__global__ void __launch_bounds__(768) norm_kernel(const float* __restrict__ gal,
                                                   const float* __restrict__ prob) {
    __shared__ float ssum[16][48];
    int b = blockIdx.x;                 // 0..127
    int tx = threadIdx.x;               // 0..47
    int ty = threadIdx.y;               // 0..15
    int j = blockIdx.y * 48 + tx;       // 0..191
    const float* src = (b < 64) ? (gal + (size_t)b * D_ * HW_)
                                : (prob + (size_t)(b - 64) * D_ * HW_);
    float ss = 0.f;
#pragma unroll
    for (int dd = 0; dd < 32; dd++) {
        float v = src[(size_t)(ty * 32 + dd) * HW_ + j];
        ss += v * v;
    }
    ssum[ty][tx] = ss;
    __syncthreads();
    if (ty == 0) {
        float s = 0.f;
#pragma unroll
        for (int k = 0; k < 16; k++) s += ssum[k][tx];
        g_scale[b * HW_ + j] = 1.f / fmaxf(sqrtf(s), 1e-12f);
    }
}

// ------------------ Kernel 2: transpose + scale + f16 ----------------------
__global__ void prep_kernel(const float* __restrict__ gal,
                            const float* __restrict__ prob) {
    __shared__ float tile[32][33];
    __shared__ float fj[32];
    int z = blockIdx.z;                 // 0..127
    int d0 = blockIdx.x * 32;           // 16 tiles
    int j0 = blockIdx.y * 32;           // 6 tiles
    int tx = threadIdx.x, ty = threadIdx.y;  // 32 x 8
    const float* src;
    __half* dst;
    if (z < 64) {
        src = gal + (size_t)z * D_ * HW_;
        dst = g_galB + (size_t)z * HW_ * D_;
    } else {
        src = prob + (size_t)(z - 64) * D_ * HW_;
        dst = g_kerA + (size_t)(z - 64) * HW_ * D_;
    }
#pragma unroll
    for (int r = 0; r < 32; r += 8)
        tile[ty + r][tx] = src[(size_t)(d0 + ty + r) * HW_ + j0 + tx];
    if (ty == 0) fj[tx] = g_scale[z * HW_ + j0 + tx];
    __syncthreads();

    int tid = ty * 32 + tx;
    int jl = tid >> 3;                  // 0..31 (j within tile)
    int d4 = (tid & 7) * 4;             // 0,4,..,28 (d within tile)
    float f = fj[jl];
    __half2 lo = __floats2half2_rn(tile[d4 + 0][jl] * f, tile[d4 + 1][jl] * f);
    __half2 hi = __floats2half2_rn(tile[d4 + 2][jl] * f, tile[d4 + 3][jl] * f);
    uint2 packed = make_uint2(*(uint32_t*)&lo, *(uint32_t*)&hi);
    *(uint2*)(dst + (size_t)(j0 + jl) * D_ + d0 + d4) = packed;
}

// ------------------------------ helpers ------------------------------
__device__ __forceinline__ uint32_t smem_u32(const void* p) {
    return (uint32_t)__cvta_generic_to_shared(p);
}
__device__ __forceinline__ void cpasync16(uint32_t dst, const void* src) {
    asm volatile("cp.async.cg.shared.global [%0], [%1], 16;"
                 :: "r"(dst), "l"(src) : "memory");
}
__device__ __forceinline__ void ldsm4(uint32_t& r0, uint32_t& r1,
                                      uint32_t& r2, uint32_t& r3,
                                      uint32_t addr) {
    asm volatile("ldmatrix.sync.aligned.m8n8.x4.shared.b16 {%0,%1,%2,%3}, [%4];"
                 : "=r"(r0), "=r"(r1), "=r"(r2), "=r"(r3) : "r"(addr));
}
// f16 x f16 -> f16 accumulate. D/C = 2x b32 (4 halves):
//   reg0 = {(row r, col c), (row r, col c+1)}
//   reg1 = {(row r+8, col c), (row r+8, col c+1)}
__device__ __forceinline__ void mma16816h(uint32_t* c, const uint32_t* a,
                                          uint32_t b0, uint32_t b1) {
    asm volatile(
        "mma.sync.aligned.m16n8k16.row.col.f16.f16.f16.f16 "
        "{%0,%1}, {%2,%3,%4,%5}, {%6,%7}, {%0,%1};"
        : "+r"(c[0]), "+r"(c[1])
        : "r"(a[0]), "r"(a[1]), "r"(a[2]), "r"(a[3]), "r"(b0), "r"(b1));
}

#define SWZ(x) ((x) ^ (((x) >> 3) & 0x70))

// SMEM: 3-stage ring; stage = A 192x128B (24KB) + B 192x128B (24KB) = 48KB
#define OFF_BUF    1024
#define CH_BYTES   49152
#define STG(s)     (OFF_BUF + (s) * CH_BYTES)
#define OFF_ROWP   (OFF_BUF + 3 * CH_BYTES)            // rowp[2][192] f32
#define OFF_COLP   (OFF_ROWP + 2 * 192 * 4)            // colp[4][192] f32
#define OFF_RED    (OFF_COLP + 4 * 192 * 4)            // red[8]
#define SMEM_BYTES (OFF_RED + 64)

// Issue all cp.async for chunk c (K in [c*64,(c+1)*64)) of `pair` into stage st
__device__ __forceinline__ void load_chunk(uint32_t sbase, int pair, int c,
                                           int st, int tid) {
    const __half* Ag = g_kerA + (size_t)(pair & 63) * HW_ * D_;
    const __half* Bg = g_galB + (size_t)(pair >> 6) * HW_ * D_;
    const uint32_t sb_ = sbase + STG(st);
#pragma unroll
    for (int i = 0; i < 12; i++) {
        int gid2 = tid + i * 256;
        bool isA = gid2 < 1536;
        int lg = isA ? gid2 : gid2 - 1536;
        int row = lg >> 3, seg = lg & 7;
        const __half* src =
            (isA ? Ag : Bg) + (size_t)row * D_ + c * 64 + seg * 8;
        uint32_t dst = sb_ + (isA ? 0 : 24576) + SWZ(row * 128 + seg * 16);
        cpasync16(dst, src);
    }
    asm volatile("cp.async.commit_group;" ::: "memory");
}

// ----------------- Kernel 3: persistent GEMM + fused epilogue -------------
__global__ void __launch_bounds__(256, 1) qaconv_gemm(
    const float* __restrict__ bnw, const float* __restrict__ bnb,
    const float* __restrict__ bnm, const float* __restrict__ bnv,
    const float* __restrict__ fcw, const float* __restrict__ fcb,
    const float* __restrict__ lbnw, const float* __restrict__ lbnb,
    const float* __restrict__ lbnm, const float* __restrict__ lbnv,
    float* __restrict__ out)
{
    extern __shared__ char smem[];
    const uint32_t sbase = smem_u32(smem);
    const int tid = threadIdx.x;
    const int wid = tid >> 5;
    const int lane = tid & 31;
    const int warp_m = wid & 3;        // 4 strips of 48 rows (probe i)
    const int warp_n = wid >> 2;       // 2 strips of 96 cols (gallery j)
    const int bid = blockIdx.x;
    const int gstride = gridDim.x;

    const int T = (NPAIR - bid + gstride - 1) / gstride;   // pairs for this CTA
    if (T <= 0) return;
    const int lastLc = T * 8 - 1;

    const float a_bn = bnw[0] * rsqrtf(bnv[0] + 1e-5f);
    const float b_bn = bnb[0] - bnm[0] * a_bn;
    const float a_lbn = lbnw[0] * rsqrtf(lbnv[0] + 1e-5f);
    const float b0_lbn = lbnb[0] - lbnm[0] * a_lbn;
    const float fcb0 = fcb[0];

    float* rowp = (float*)(smem + OFF_ROWP);   // [2][192]
    float* colp = (float*)(smem + OFF_COLP);   // [4][192]
    float* red  = (float*)(smem + OFF_RED);

    // prologue: first two chunks of first pair
    load_chunk(sbase, bid, 0, 0, tid);
    load_chunk(sbase, bid, 1, 1, tid);

#pragma unroll 1
    for (int t = 0; t < T; t++) {
        const int pair = bid + t * gstride;

        uint32_t acc[3][12][2];          // f16x2 accumulators
#pragma unroll
        for (int mt = 0; mt < 3; mt++)
#pragma unroll
            for (int nt = 0; nt < 12; nt++) {
                acc[mt][nt][0] = 0u;
                acc[mt][nt][1] = 0u;
            }

#pragma unroll 1
        for (int c = 0; c < 8; c++) {
            const int lc = t * 8 + c;
            if (lc == lastLc)
                asm volatile("cp.async.wait_group 0;" ::: "memory");
            else
                asm volatile("cp.async.wait_group 1;" ::: "memory");
            __syncthreads();

            const uint32_t ab = sbase + STG(lc % 3);
            const uint32_t bb = ab + 24576;
            const int arowb = (warp_m * 48 + (lane & 15)) * 128;
            const int brow  = warp_n * 96 + (lane & 7) + ((lane >> 4) << 3);
#pragma unroll
            for (int ks = 0; ks < 4; ks++) {
                const int akb = ks * 32 + ((lane >> 4) << 4);
                const int bkb = ks * 32 + (((lane >> 3) & 1) << 4);
                uint32_t a[3][4];
#pragma unroll
                for (int mt = 0; mt < 3; mt++)
                    ldsm4(a[mt][0], a[mt][1], a[mt][2], a[mt][3],
                          ab + SWZ(arowb + mt * 2048 + akb));
                uint32_t bf[6][4];
#pragma unroll
                for (int nt2 = 0; nt2 < 6; nt2++)
                    ldsm4(bf[nt2][0], bf[nt2][1], bf[nt2][2], bf[nt2][3],
                          bb + SWZ((brow + nt2 * 16) * 128 + bkb));
#pragma unroll
                for (int mt = 0; mt < 3; mt++)
#pragma unroll
                    for (int nt2 = 0; nt2 < 6; nt2++) {
                        mma16816h(acc[mt][nt2 * 2 + 0], a[mt], bf[nt2][0], bf[nt2][1]);
                        mma16816h(acc[mt][nt2 * 2 + 1], a[mt], bf[nt2][2], bf[nt2][3]);
                    }
            }
            // prefetch chunk lc+2 (may belong to the next pair); target stage
            // (lc+2)%3 == (lc-1)%3 is the PREVIOUS chunk's stage, already
            // consumed by all warps (fenced by this iteration's __syncthreads)
            const int lcn = lc + 2;
            if (lcn <= lastLc) {
                const int pairN = bid + (lcn >> 3) * gstride;
                load_chunk(sbase, pairN, lcn & 7, lcn % 3, tid);
            }
        }

        // -------- epilogue: dual max + BN/fc/LBN/sigmoid (overlaps next loads)
        // acc[mt][nt][0] = {(r,c),(r,c+1)}, [1] = {(r+8,c),(r+8,c+1)}
        //   r = warp_m*48 + mt*16 + lane/4, c = warp_n*96 + nt*8 + (lane%4)*2
        const __half2 NEGINF = __float2half2_rn(-60000.f);

        float rm[6];
#pragma unroll
        for (int mt = 0; mt < 3; mt++) {
            __half2 m0 = NEGINF, m1 = NEGINF;
#pragma unroll
            for (int nt = 0; nt < 12; nt++) {
                m0 = __hmax2(m0, *(__half2*)&acc[mt][nt][0]);
                m1 = __hmax2(m1, *(__half2*)&acc[mt][nt][1]);
            }
            rm[2 * mt]     = fmaxf(__low2float(m0), __high2float(m0));
            rm[2 * mt + 1] = fmaxf(__low2float(m1), __high2float(m1));
        }
#pragma unroll
        for (int i = 0; i < 6; i++) {
            rm[i] = fmaxf(rm[i], __shfl_xor_sync(0xffffffffu, rm[i], 1));
            rm[i] = fmaxf(rm[i], __shfl_xor_sync(0xffffffffu, rm[i], 2));
        }
        if ((lane & 3) == 0) {
            int rbase = warp_m * 48 + (lane >> 2);
#pragma unroll
            for (int mt = 0; mt < 3; mt++) {
                rowp[warp_n * 192 + rbase + mt * 16]     = rm[2 * mt];
                rowp[warp_n * 192 + rbase + mt * 16 + 8] = rm[2 * mt + 1];
            }
        }

        float cm[24];
#pragma unroll
        for (int nt = 0; nt < 12; nt++) {
            __half2 mc = NEGINF;
#pragma unroll
            for (int mt = 0; mt < 3; mt++)
                mc = __hmax2(mc, __hmax2(*(__half2*)&acc[mt][nt][0],
                                         *(__half2*)&acc[mt][nt][1]));
            cm[2 * nt]     = __low2float(mc);
            cm[2 * nt + 1] = __high2float(mc);
        }
#pragma unroll
        for (int i = 0; i < 24; i++) {
            cm[i] = fmaxf(cm[i], __shfl_xor_sync(0xffffffffu, cm[i], 4));
            cm[i] = fmaxf(cm[i], __shfl_xor_sync(0xffffffffu, cm[i], 8));
            cm[i] = fmaxf(cm[i], __shfl_xor_sync(0xffffffffu, cm[i], 16));
        }
        if (lane < 4) {
            int cbase = warp_n * 96 + lane * 2;
#pragma unroll
            for (int nt = 0; nt < 12; nt++) {
                colp[warp_m * 192 + cbase + nt * 8]     = cm[2 * nt];
                colp[warp_m * 192 + cbase + nt * 8 + 1] = cm[2 * nt + 1];
            }
        }
        __syncthreads();

        float part = 0.f;
        if (tid < 192) {
            float cmax = fmaxf(fmaxf(colp[tid], colp[192 + tid]),
                               fmaxf(colp[384 + tid], colp[576 + tid]));
            float rmax = fmaxf(rowp[tid], rowp[192 + tid]);
            part = fcw[tid]       * (a_bn * cmax + b_bn)   // s.max(axis=2), idx j
                 + fcw[192 + tid] * (a_bn * rmax + b_bn);  // s.max(axis=3), idx i
        }
#pragma unroll
        for (int o = 16; o > 0; o >>= 1)
            part += __shfl_down_sync(0xffffffffu, part, o);
        if (lane == 0) red[wid] = part;
        __syncthreads();
        if (tid == 0) {
            float s = red[0] + red[1] + red[2] + red[3] +
                      red[4] + red[5] + red[6] + red[7];
            s += fcb0;
            float y = s * a_lbn + b0_lbn;
            out[pair] = 1.f / (1.f + expf(-y * 0.1f));
        }
    }
}

// ------------------------------ launch ---------------------------------------
extern "C" void kernel_launch(void* const* d_in, const int* in_sizes, int n_in,
                              void* d_out, int out_size) {
    const float* gal  = (const float*)d_in[0];
    const float* prob = (const float*)d_in[1];
    const float* bnw  = (const float*)d_in[2];
    const float* bnb  = (const float*)d_in[3];
    const float* bnm  = (const float*)d_in[4];
    const float* bnv  = (const float*)d_in[5];
    const float* fcw  = (const float*)d_in[6];
    const float* fcb  = (const float*)d_in[7];
    const float* lbnw = (const float*)d_in[8];
    const float* lbnb = (const float*)d_in[9];
    const float* lbnm = (const float*)d_in[10];
    const float* lbnv = (const float*)d_in[11];
    float* out = (float*)d_out;

    int sms = 0;
    cudaDeviceGetAttribute(&sms, cudaDevAttrMultiProcessorCount, 0);
    if (sms <= 0) sms = 148;
    if (sms > NPAIR) sms = NPAIR;

    cudaFuncSetAttribute(qaconv_gemm, cudaFuncAttributeMaxDynamicSharedMemorySize,
                         SMEM_BYTES);

    norm_kernel<<<dim3(128, 4), dim3(48, 16)>>>(gal, prob);
    prep_kernel<<<dim3(16, 6, 128), dim3(32, 8)>>>(gal, prob);
    qaconv_gemm<<<sms, 256, SMEM_BYTES>>>(bnw, bnb, bnm, bnv, fcw, fcb,
                                          lbnw, lbnb, lbnm, lbnv, out);
}